// round 3
// baseline (speedup 1.0000x reference)
#include <cuda_runtime.h>
#include <math.h>

#define B_   32
#define T_   1000
#define F_   80
#define H_   1024
#define HH_  2048
#define NBLK 128
#define EPSV 1e-5f

typedef unsigned long long ull;

// ---------------- scratch (static device globals; no allocation) ----------------
__device__ float g_w[65536000];          // [32000][2048]
__device__ float g_hs1[32768000];        // [32000][1024]
__device__ float g_hT[H_ * B_];          // transposed h: [k=1024][i=32]
__device__ float g_colsum[HH_];
__device__ float g_colsq[HH_];
__device__ float g_scale[HH_];
__device__ float g_shift[HH_];
__device__ float g_psum[B_ * NBLK];
__device__ float g_psq[B_ * NBLK];
__device__ unsigned g_bar_cnt = 0;
__device__ unsigned g_bar_gen = 0;

// ---------------- helpers ----------------
union F4U { float4 f; ulonglong2 u; };

__device__ __forceinline__ void fma2(ull& d, ull a, ull b) {
    asm("fma.rn.f32x2 %0, %1, %2, %0;" : "+l"(d) : "l"(a), "l"(b));
}
__device__ __forceinline__ float ulo(ull v) { return __uint_as_float((unsigned)v); }
__device__ __forceinline__ float uhi(ull v) { return __uint_as_float((unsigned)(v >> 32)); }

__device__ __forceinline__ void gridbar() {
    __syncthreads();
    if (threadIdx.x == 0) {
        volatile unsigned* genp = &g_bar_gen;
        unsigned gen = *genp;
        __threadfence();
        unsigned arr = atomicAdd(&g_bar_cnt, 1u);
        if (arr == NBLK - 1) {
            g_bar_cnt = 0;
            __threadfence();
            atomicAdd(&g_bar_gen, 1u);
        } else {
            while (*genp == gen) { }
            __threadfence();
        }
    }
    __syncthreads();
}

// ---------------- SGEMM (NT) with f32x2: C[m][n] = sum_k A[m][k]*B[n][k], N=2048 ----------------
__global__ void __launch_bounds__(256)
sgemm_nt(const float* __restrict__ A, const float* __restrict__ Bm,
         float* __restrict__ C, int K)
{
    __shared__ float Asd[8][256];   // A rows duplicated as (v,v) pairs
    __shared__ float Bs[8][128];
    const int tid  = threadIdx.x;
    const int m0   = blockIdx.y * 128;
    const int n0   = blockIdx.x * 128;
    const int lrow = tid >> 1;
    const int lk4  = (tid & 1) * 4;
    const int tx   = tid & 15, ty = tid >> 4;
    const float* Ap = A  + (size_t)(m0 + lrow) * K + lk4;
    const float* Bp = Bm + (size_t)(n0 + lrow) * K + lk4;

    ull accp[8][4];
    #pragma unroll
    for (int i = 0; i < 8; i++)
        #pragma unroll
        for (int j = 0; j < 4; j++) accp[i][j] = 0ull;

    for (int k0 = 0; k0 < K; k0 += 8) {
        float4 av = *(const float4*)(Ap + k0);
        float4 bv = *(const float4*)(Bp + k0);
        __syncthreads();
        Asd[lk4 + 0][lrow * 2] = av.x; Asd[lk4 + 0][lrow * 2 + 1] = av.x;
        Asd[lk4 + 1][lrow * 2] = av.y; Asd[lk4 + 1][lrow * 2 + 1] = av.y;
        Asd[lk4 + 2][lrow * 2] = av.z; Asd[lk4 + 2][lrow * 2 + 1] = av.z;
        Asd[lk4 + 3][lrow * 2] = av.w; Asd[lk4 + 3][lrow * 2 + 1] = av.w;
        Bs[lk4 + 0][lrow] = bv.x; Bs[lk4 + 1][lrow] = bv.y;
        Bs[lk4 + 2][lrow] = bv.z; Bs[lk4 + 3][lrow] = bv.w;
        __syncthreads();
        #pragma unroll
        for (int kk = 0; kk < 8; kk++) {
            F4U a0, a1, a2, a3, b0, b1;
            a0.f = *(const float4*)&Asd[kk][ty * 16 + 0];
            a1.f = *(const float4*)&Asd[kk][ty * 16 + 4];
            a2.f = *(const float4*)&Asd[kk][ty * 16 + 8];
            a3.f = *(const float4*)&Asd[kk][ty * 16 + 12];
            b0.f = *(const float4*)&Bs[kk][tx * 8];
            b1.f = *(const float4*)&Bs[kk][tx * 8 + 4];
            ull ap[8] = {a0.u.x, a0.u.y, a1.u.x, a1.u.y, a2.u.x, a2.u.y, a3.u.x, a3.u.y};
            ull bp[4] = {b0.u.x, b0.u.y, b1.u.x, b1.u.y};
            #pragma unroll
            for (int i = 0; i < 8; i++)
                #pragma unroll
                for (int j = 0; j < 4; j++)
                    fma2(accp[i][j], ap[i], bp[j]);
        }
    }
    #pragma unroll
    for (int i = 0; i < 8; i++) {
        float* Cp = C + (size_t)(m0 + ty * 8 + i) * HH_ + n0 + tx * 8;
        ulonglong2 s0; s0.x = accp[i][0]; s0.y = accp[i][1];
        ulonglong2 s1; s1.x = accp[i][2]; s1.y = accp[i][3];
        *(ulonglong2*)Cp       = s0;
        *(ulonglong2*)(Cp + 4) = s1;
    }
}

// ---------------- BatchNorm column stats over 32000 rows ----------------
__global__ void __launch_bounds__(256)
bn_stats(const float* __restrict__ w)
{
    int col = blockIdx.x * 256 + threadIdx.x;
    size_t r0 = (size_t)blockIdx.y * 1000;
    float s = 0.0f, q = 0.0f;
    const float* p = w + r0 * HH_ + col;
    #pragma unroll 4
    for (int r = 0; r < 1000; r++) {
        float v = p[(size_t)r * HH_];
        s += v; q += v * v;
    }
    atomicAdd(&g_colsum[col], s);
    atomicAdd(&g_colsq[col], q);
}

__global__ void __launch_bounds__(256)
bn_finalize(const float* __restrict__ gamma, const float* __restrict__ beta)
{
    int c = blockIdx.x * 256 + threadIdx.x;
    float mean = g_colsum[c] * (1.0f / 32000.0f);
    float var  = g_colsq[c] * (1.0f / 32000.0f) - mean * mean;
    float sc = gamma[c] * rsqrtf(var + EPSV);
    g_scale[c] = sc;
    g_shift[c] = beta[c] - mean * sc;
}

// ---------------- Persistent LiGRU recurrence (512 threads, f32x2 GEMM) ----------------
// SMEM floats:
//   Udup  [1024][16] float2  @ 0       (131072 B / 32768 floats)
//   red   [16][512]          @ 32768   (32768 B / 8192 floats)
//   uhbuf [512]              @ 40960
//   smean [32]               @ 41472
//   srstd [32]               @ 41504
//   scs   [16]               @ 41536
//   shs   [16]               @ 41552   -> 41568 floats = 166272 B
#define REC_SMEM_FLOATS 41568

__global__ void __launch_bounds__(512, 1)
rec_kernel(const float* __restrict__ w, const float* __restrict__ U,
           float* __restrict__ hs_out)
{
    extern __shared__ float sm[];
    float* Udup  = sm;            // float2 pairs, addressed in floats
    float* red   = sm + 32768;
    float* uhbuf = sm + 40960;
    float* smean = sm + 41472;
    float* srstd = sm + 41504;
    float* scs   = sm + 41536;
    float* shs   = sm + 41552;

    const int tid = threadIdx.x;
    const int b   = blockIdx.x;
    const int cb  = b * 8;

    // One-time: U slice transposed + duplicated pairs; fold BN scale/shift
    for (int idx = tid; idx < 16 * 1024; idx += 512) {
        int jj = idx >> 10, k = idx & 1023;
        int urow = (jj < 8) ? (cb + jj) : (H_ + cb + jj - 8);
        float v = U[(size_t)urow * H_ + k];
        Udup[(k * 16 + jj) * 2]     = v;
        Udup[(k * 16 + jj) * 2 + 1] = v;
    }
    if (tid < 16) {
        int col = (tid < 8) ? (cb + tid) : (H_ + cb + tid - 8);
        scs[tid] = g_scale[col];
        shs[tid] = g_shift[col];
    }
    __syncthreads();

    const int warp  = tid >> 5, lane = tid & 31;
    const int i0    = (lane & 7) * 4;     // 4 batch rows (2 f32x2 pairs)
    const int jj0   = (lane >> 3) * 4;    // 4 gate cols
    const int kbase = warp * 64;          // K segment per warp

    const int ui = tid >> 3;              // update-phase batch row (threads < 256)
    const int uj = tid & 7;               // update-phase h-col within block

    float hreg = 0.0f;

    const float* hseg = g_hT + kbase * B_ + i0;
    const float* useg = Udup + (kbase * 16 + jj0) * 2;

    for (int t = 0; t < T_; ++t) {
        // -- prefetch this step's w (consumed in update; hides DRAM latency) --
        float wa_raw = 0.0f, wz_raw = 0.0f;
        if (tid < 256) {
            size_t wrow = (size_t)(ui * T_ + t) * HH_;
            wa_raw = __ldg(w + wrow + cb + uj);
            wz_raw = __ldg(w + wrow + H_ + cb + uj);
        }

        // -- per-warp partial GEMM over K segment (f32x2) --
        ull acc[2][4];
        #pragma unroll
        for (int p = 0; p < 2; p++)
            #pragma unroll
            for (int j = 0; j < 4; j++) acc[p][j] = 0ull;

        #pragma unroll 4
        for (int ku = 0; ku < 64; ku += 4) {
            F4U hv[4], ua[4], ub[4];
            #pragma unroll
            for (int u = 0; u < 4; u++)
                hv[u].f = __ldcg((const float4*)(hseg + (ku + u) * B_));
            #pragma unroll
            for (int u = 0; u < 4; u++) {
                ua[u].f = *(const float4*)(useg + (ku + u) * 32);
                ub[u].f = *(const float4*)(useg + (ku + u) * 32 + 4);
            }
            #pragma unroll
            for (int u = 0; u < 4; u++) {
                fma2(acc[0][0], hv[u].u.x, ua[u].u.x);
                fma2(acc[1][0], hv[u].u.y, ua[u].u.x);
                fma2(acc[0][1], hv[u].u.x, ua[u].u.y);
                fma2(acc[1][1], hv[u].u.y, ua[u].u.y);
                fma2(acc[0][2], hv[u].u.x, ub[u].u.x);
                fma2(acc[1][2], hv[u].u.y, ub[u].u.x);
                fma2(acc[0][3], hv[u].u.x, ub[u].u.y);
                fma2(acc[1][3], hv[u].u.y, ub[u].u.y);
            }
        }
        {
            float4 r0 = make_float4(ulo(acc[0][0]), ulo(acc[0][1]), ulo(acc[0][2]), ulo(acc[0][3]));
            float4 r1 = make_float4(uhi(acc[0][0]), uhi(acc[0][1]), uhi(acc[0][2]), uhi(acc[0][3]));
            float4 r2 = make_float4(ulo(acc[1][0]), ulo(acc[1][1]), ulo(acc[1][2]), ulo(acc[1][3]));
            float4 r3 = make_float4(uhi(acc[1][0]), uhi(acc[1][1]), uhi(acc[1][2]), uhi(acc[1][3]));
            float* rp = red + warp * 512 + i0 * 16 + jj0;
            *(float4*)(rp)      = r0;
            *(float4*)(rp + 16) = r1;
            *(float4*)(rp + 32) = r2;
            *(float4*)(rp + 48) = r3;
        }
        __syncthreads();

        // -- cross-warp K reduction + LN partials via half-warp shuffles --
        {
            float v = red[tid];
            #pragma unroll
            for (int wv = 1; wv < 16; wv++) v += red[wv * 512 + tid];
            uhbuf[tid] = v;
            float S = v, Q = v * v;
            #pragma unroll
            for (int d = 8; d >= 1; d >>= 1) {
                S += __shfl_xor_sync(0xffffffffu, S, d, 16);
                Q += __shfl_xor_sync(0xffffffffu, Q, d, 16);
            }
            if ((tid & 15) == 0) {
                int i = tid >> 4;
                g_psum[i * NBLK + b] = S;
                g_psq [i * NBLK + b] = Q;
            }
        }
        gridbar();   // (A) all blocks' LN partials visible

        // -- global LN stats reduce (128 partials per row) --
        if (tid < 256) {
            int i = tid >> 3, p = tid & 7;
            const float* ps = g_psum + i * NBLK + p * 16;
            const float* pq = g_psq  + i * NBLK + p * 16;
            float S = 0.f, Q = 0.f;
            #pragma unroll
            for (int q = 0; q < 16; q++) { S += __ldcg(ps + q); Q += __ldcg(pq + q); }
            #pragma unroll
            for (int d = 4; d >= 1; d >>= 1) {
                S += __shfl_xor_sync(0xffffffffu, S, d, 8);
                Q += __shfl_xor_sync(0xffffffffu, Q, d, 8);
            }
            if (p == 0) {
                float mean = S * (1.0f / 2048.0f);
                float var  = Q * (1.0f / 2048.0f) - mean * mean;
                smean[i] = mean;
                srstd[i] = rsqrtf(var + EPSV);
            }
        }
        __syncthreads();

        // -- gate + h update (h carried in register) --
        if (tid < 256) {
            float m = smean[ui], r = srstd[ui];
            float an = (uhbuf[ui * 16 + uj]     - m) * r;
            float zn = (uhbuf[ui * 16 + 8 + uj] - m) * r;
            float wa = wa_raw * scs[uj]     + shs[uj];
            float wz = wz_raw * scs[8 + uj] + shs[8 + uj];
            float a  = wa + an;
            float zx = wz + zn;
            float z  = 1.0f / (1.0f + __expf(-zx));
            float hnew = z * hreg + (1.0f - z) * fmaxf(a, 0.0f);
            hreg = hnew;
            g_hT[(cb + uj) * B_ + ui] = hnew;
            hs_out[(size_t)(ui * T_ + t) * H_ + cb + uj] = hnew;
        }
        gridbar();   // (B) new h visible before next step's GEMM reads
    }
}

// ---------------- launch ----------------
extern "C" void kernel_launch(void* const* d_in, const int* in_sizes, int n_in,
                              void* d_out, int out_size)
{
    const float* x  = (const float*)d_in[0];
    const float* W1 = (const float*)d_in[1];
    const float* U1 = (const float*)d_in[2];
    const float* g1 = (const float*)d_in[3];
    const float* b1 = (const float*)d_in[4];
    const float* W2 = (const float*)d_in[5];
    const float* U2 = (const float*)d_in[6];
    const float* g2 = (const float*)d_in[7];
    const float* b2 = (const float*)d_in[8];
    float* out = (float*)d_out;

    float *w_buf, *hs1, *csum, *csq, *hT;
    cudaGetSymbolAddress((void**)&w_buf, g_w);
    cudaGetSymbolAddress((void**)&hs1,   g_hs1);
    cudaGetSymbolAddress((void**)&csum,  g_colsum);
    cudaGetSymbolAddress((void**)&csq,   g_colsq);
    cudaGetSymbolAddress((void**)&hT,    g_hT);

    cudaFuncSetAttribute(rec_kernel, cudaFuncAttributeMaxDynamicSharedMemorySize,
                         REC_SMEM_FLOATS * 4);

    dim3 gproj(16, 250);

    // ---- Layer 1 ----
    sgemm_nt<<<gproj, 256>>>(x, W1, w_buf, F_);
    cudaMemsetAsync(csum, 0, HH_ * 4);
    cudaMemsetAsync(csq,  0, HH_ * 4);
    bn_stats<<<dim3(8, 32), 256>>>(w_buf);
    bn_finalize<<<8, 256>>>(g1, b1);
    cudaMemsetAsync(hT, 0, H_ * B_ * 4);
    rec_kernel<<<NBLK, 512, REC_SMEM_FLOATS * 4>>>(w_buf, U1, hs1);

    // ---- Layer 2 ----
    sgemm_nt<<<gproj, 256>>>(hs1, W2, w_buf, H_);
    cudaMemsetAsync(csum, 0, HH_ * 4);
    cudaMemsetAsync(csq,  0, HH_ * 4);
    bn_stats<<<dim3(8, 32), 256>>>(w_buf);
    bn_finalize<<<8, 256>>>(g2, b2);
    cudaMemsetAsync(hT, 0, H_ * B_ * 4);
    rec_kernel<<<NBLK, 512, REC_SMEM_FLOATS * 4>>>(w_buf, U2, out);

    (void)in_sizes; (void)n_in; (void)out_size;
}